// round 11
// baseline (speedup 1.0000x reference)
#include <cuda_runtime.h>
#include <math.h>

#ifndef M_PI
#define M_PI 3.14159265358979323846
#endif

#define BATCH      256
#define T_LEN      65536
#define L_CHUNK    32
#define W_WARM     32                      // window = exactly previous chunk
#define CPB        128                     // chunks (= threads) per block
#define REGION     (CPB * L_CHUNK)         // 4096 floats = 16KB
#define RB_PER_ROW (T_LEN / REGION)        // 16 blocks per batch row
#define NBLK       (BATCH * RB_PER_ROW)    // 4096 blocks

struct Params {
    float b0, b1, b2, b3, b4;      // numerator
    float na1, na2, na3, na4;      // negated denominator taps
    float4 wq4[W_WARM];            // warmup weights w_j = A^(W-1-j) g (const space)
};

// 16B-granule swizzle: word (chunk c, sample j) -> c*32 + (j ^ ((c&7)<<2)).
// XOR touches only bits 2..4 (j<32), aligned float4 groups stay contiguous,
// and every phase of every 128-bit smem op below is bank-conflict-free.
__device__ __forceinline__ int sidx4(int c, int j) {
    return c * L_CHUNK + (j ^ ((c & 7) << 2));
}

__device__ __forceinline__ void cpa16(unsigned dst_smem, const void* src) {
    asm volatile("cp.async.cg.shared.global [%0], [%1], 16;\n"
                 :: "r"(dst_smem), "l"(src));
}

__global__ void __launch_bounds__(CPB, 10) fused_kernel(const float* __restrict__ x,
                                                        float* __restrict__ y,
                                                        Params P) {
    // main region + 32-float pad region (words REGION..REGION+31) for the
    // block-leading chunk's warmup window; unified addressing (wk = 0 there).
    __shared__ float4 smv[(REGION + W_WARM) / 4];
    float* sm = reinterpret_cast<float*>(smv);

    const int t   = threadIdx.x;
    const int blk = blockIdx.x;
    const int rb  = blk & (RB_PER_ROW - 1);
    const size_t gbase = (size_t)(blk >> 4) * T_LEN + (size_t)rb * REGION;

    // ---- stage: coalesced 16B cp.async -> swizzled smem ----
    const float4* xin = reinterpret_cast<const float4*>(x + gbase);
    unsigned smb = (unsigned)__cvta_generic_to_shared(sm);
#pragma unroll
    for (int i = 0; i < REGION / (4 * CPB); i++) {   // 8 iters
        int vidx = i * CPB + t;
        int c = vidx >> 3;                // 8 float4 per chunk
        int j = (vidx & 7) * 4;
        cpa16(smb + sidx4(c, j) * 4u, xin + vidx);
    }
    if (t < W_WARM / 4) {                 // pad: x[block_start-32 .. -1]
        float4 d = make_float4(0.f, 0.f, 0.f, 0.f);
        if (rb != 0)
            d = reinterpret_cast<const float4*>(x + gbase - W_WARM)[t];
        reinterpret_cast<float4*>(&sm[REGION])[t] = d;
    }
    asm volatile("cp.async.commit_group;\n");
    asm volatile("cp.async.wait_group 0;\n");
    __syncthreads();

    // ---- warmup: state = sum over previous 32 samples, w_j = A^(31-j) g ----
    // Window == previous chunk (t>0) or the pad region (t==0; zeros at row
    // start reproduce the zero-initial-condition state exactly).
    float z0 = 0.f, z1 = 0.f, z2 = 0.f, z3 = 0.f;
    {
        const int wbase = (t > 0) ? (t - 1) * L_CHUNK : REGION;
        const int wk    = (t > 0) ? ((t - 1) & 7) << 2 : 0;
#pragma unroll
        for (int q = 0; q < W_WARM / 4; q++) {
            float4 xv = *reinterpret_cast<const float4*>(&sm[wbase + ((4 * q) ^ wk)]);
            float4 w0 = P.wq4[4 * q + 0], w1 = P.wq4[4 * q + 1];
            float4 w2 = P.wq4[4 * q + 2], w3 = P.wq4[4 * q + 3];
            z0 = fmaf(w0.x, xv.x, z0); z1 = fmaf(w0.y, xv.x, z1);
            z2 = fmaf(w0.z, xv.x, z2); z3 = fmaf(w0.w, xv.x, z3);
            z0 = fmaf(w1.x, xv.y, z0); z1 = fmaf(w1.y, xv.y, z1);
            z2 = fmaf(w1.z, xv.y, z2); z3 = fmaf(w1.w, xv.y, z3);
            z0 = fmaf(w2.x, xv.z, z0); z1 = fmaf(w2.y, xv.z, z1);
            z2 = fmaf(w2.z, xv.z, z2); z3 = fmaf(w2.w, xv.z, z3);
            z0 = fmaf(w3.x, xv.w, z0); z1 = fmaf(w3.y, xv.w, z1);
            z2 = fmaf(w3.z, xv.w, z2); z3 = fmaf(w3.w, xv.w, z3);
        }
    }
    __syncthreads();   // all warmup reads done before in-place overwrite

    // ---- main: DF2T over own chunk (vectorized smem IO), y in place ----
#pragma unroll
    for (int q = 0; q < L_CHUNK / 4; q++) {
        float4* ap = reinterpret_cast<float4*>(&sm[sidx4(t, 4 * q)]);
        float4 xv = *ap;
        float4 ov;
        {   float xvv = xv.x;
            float yv = fmaf(P.b0, xvv, z0);
            z0 = fmaf(P.b1, xvv, z1); z0 = fmaf(P.na1, yv, z0);
            z1 = fmaf(P.b2, xvv, z2); z1 = fmaf(P.na2, yv, z1);
            z2 = fmaf(P.b3, xvv, z3); z2 = fmaf(P.na3, yv, z2);
            z3 = P.b4 * xvv;          z3 = fmaf(P.na4, yv, z3);
            ov.x = yv; }
        {   float xvv = xv.y;
            float yv = fmaf(P.b0, xvv, z0);
            z0 = fmaf(P.b1, xvv, z1); z0 = fmaf(P.na1, yv, z0);
            z1 = fmaf(P.b2, xvv, z2); z1 = fmaf(P.na2, yv, z1);
            z2 = fmaf(P.b3, xvv, z3); z2 = fmaf(P.na3, yv, z2);
            z3 = P.b4 * xvv;          z3 = fmaf(P.na4, yv, z3);
            ov.y = yv; }
        {   float xvv = xv.z;
            float yv = fmaf(P.b0, xvv, z0);
            z0 = fmaf(P.b1, xvv, z1); z0 = fmaf(P.na1, yv, z0);
            z1 = fmaf(P.b2, xvv, z2); z1 = fmaf(P.na2, yv, z1);
            z2 = fmaf(P.b3, xvv, z3); z2 = fmaf(P.na3, yv, z2);
            z3 = P.b4 * xvv;          z3 = fmaf(P.na4, yv, z3);
            ov.z = yv; }
        {   float xvv = xv.w;
            float yv = fmaf(P.b0, xvv, z0);
            z0 = fmaf(P.b1, xvv, z1); z0 = fmaf(P.na1, yv, z0);
            z1 = fmaf(P.b2, xvv, z2); z1 = fmaf(P.na2, yv, z1);
            z2 = fmaf(P.b3, xvv, z3); z2 = fmaf(P.na3, yv, z2);
            z3 = P.b4 * xvv;          z3 = fmaf(P.na4, yv, z3);
            ov.w = yv; }
        *ap = ov;
    }
    __syncthreads();

    // ---- output: swizzled LDS.128 -> coalesced STG.128 ----
    float4* yout = reinterpret_cast<float4*>(y + gbase);
#pragma unroll
    for (int i = 0; i < REGION / (4 * CPB); i++) {
        int vidx = i * CPB + t;
        int c = vidx >> 3;
        int j = (vidx & 7) * 4;
        yout[vidx] = *reinterpret_cast<const float4*>(&sm[sidx4(c, j)]);
    }
}

// ---------------- host ----------------

struct Cd { double re, im; };
static inline Cd cadd(Cd a, Cd b) { return { a.re + b.re, a.im + b.im }; }
static inline Cd csub(Cd a, Cd b) { return { a.re - b.re, a.im - b.im }; }
static inline Cd cmul(Cd a, Cd b) {
    return { a.re * b.re - a.im * b.im, a.re * b.im + a.im * b.re };
}
static inline Cd cdiv(Cd a, Cd b) {
    double d = b.re * b.re + b.im * b.im;
    return { (a.re * b.re + a.im * b.im) / d, (a.im * b.re - a.re * b.im) / d };
}

extern "C" void kernel_launch(void* const* d_in, const int* in_sizes, int n_in,
                              void* d_out, int out_size) {
    const float* x = (const float*)d_in[0];
    float* y = (float*)d_out;

    // ---- Butterworth design, exactly mirroring the reference numpy math ----
    const int ORDER = 4;
    const double WN = 4000.0 / (0.5 * 16000.0);   // 0.5
    const double fs2 = 4.0;
    double warped = fs2 * tan(M_PI * WN / 4.0);

    Cd p[4];
    for (int k = 1; k <= ORDER; k++) {
        double ang = M_PI * (2 * k + ORDER - 1) / (2.0 * ORDER);
        p[k - 1] = { warped * cos(ang), warped * sin(ang) };
    }
    double gain = warped * warped * warped * warped;

    Cd pd[4];
    Cd prodden = { 1.0, 0.0 };
    for (int i = 0; i < 4; i++) {
        Cd num = cadd({ fs2, 0.0 }, p[i]);
        Cd den = csub({ fs2, 0.0 }, p[i]);
        pd[i] = cdiv(num, den);
        prodden = cmul(prodden, den);
    }
    double kd = gain / prodden.re;
    double bcoef[5] = { kd, 4.0 * kd, 6.0 * kd, 4.0 * kd, kd };

    Cd ac[5] = { {1,0}, {0,0}, {0,0}, {0,0}, {0,0} };
    for (int i = 0; i < 4; i++)
        for (int j = 4; j >= 1; j--)
            ac[j] = csub(ac[j], cmul(pd[i], ac[j - 1]));
    double acoef[5];
    for (int i = 0; i < 5; i++) acoef[i] = ac[i].re;

    // state transition: z' = A z + g x  (DF2T with y eliminated)
    double A[16] = {0};
    for (int i = 0; i < 4; i++) {
        A[i * 4 + 0] -= acoef[i + 1];
        if (i < 3) A[i * 4 + (i + 1)] += 1.0;
    }
    double g[4];
    for (int i = 0; i < 4; i++) g[i] = bcoef[i + 1] - acoef[i + 1] * bcoef[0];

    Params P;
    P.b0 = (float)bcoef[0]; P.b1 = (float)bcoef[1]; P.b2 = (float)bcoef[2];
    P.b3 = (float)bcoef[3]; P.b4 = (float)bcoef[4];
    P.na1 = (float)(-acoef[1]); P.na2 = (float)(-acoef[2]);
    P.na3 = (float)(-acoef[3]); P.na4 = (float)(-acoef[4]);

    // warmup weights: w_j = A^(W-1-j) g  (oldest sample gets highest power)
    double wv[4] = { g[0], g[1], g[2], g[3] };
    for (int j = W_WARM - 1; j >= 0; j--) {
        P.wq4[j] = make_float4((float)wv[0], (float)wv[1],
                               (float)wv[2], (float)wv[3]);
        double nv[4];
        for (int i = 0; i < 4; i++) {
            nv[i] = 0.0;
            for (int k2 = 0; k2 < 4; k2++) nv[i] += A[i * 4 + k2] * wv[k2];
        }
        for (int i = 0; i < 4; i++) wv[i] = nv[i];
    }

    fused_kernel<<<NBLK, CPB>>>(x, y, P);
}

// round 12
// speedup vs baseline: 1.0056x; 1.0056x over previous
#include <cuda_runtime.h>
#include <math.h>

#define BATCH      256
#define T_LEN      65536
#define L_CHUNK    32
#define W_WARM     32                      // window = exactly previous chunk
#define CPB        128                     // chunks (= threads) per block
#define REGION     (CPB * L_CHUNK)         // 4096 floats = 16KB
#define RB_PER_ROW (T_LEN / REGION)        // 16 blocks per batch row
#define NBLK       (BATCH * RB_PER_ROW)    // 4096 blocks

// ---- Butterworth(4, 0.5) coefficients as compile-time literals ----
// Derived from the reference math: w = 4 tan(pi/8), bilinear transform.
// Verified: sum(b) == sum(a) (DC gain 1) to 8 digits; w^4 = 4352-3072*sqrt(2).
#define KD   0.010209481f
#define CB0  (KD)
#define CB1  (4.0f * KD)
#define CB2  (6.0f * KD)
#define CB3  (4.0f * KD)
#define CB4  (KD)
#define CNA1 ( 1.96842778f)     // -a1
#define CNA2 (-1.73586071f)     // -a2
#define CNA3 ( 0.72447081f)     // -a3
#define CNA4 (-0.12038960f)     // -a4

struct Params {
    float4 wq4[W_WARM];            // warmup weights w_j = A^(W-1-j) g (const space)
};

// 16B-granule swizzle: word (chunk c, sample j) -> c*32 + (j ^ ((c&7)<<2)).
// XOR touches only bits 2..4 (j<32), aligned float4 groups stay contiguous,
// and every phase of every 128-bit smem op below is bank-conflict-free.
__device__ __forceinline__ int sidx4(int c, int j) {
    return c * L_CHUNK + (j ^ ((c & 7) << 2));
}

__device__ __forceinline__ void cpa16(unsigned dst_smem, const void* src) {
    asm volatile("cp.async.cg.shared.global [%0], [%1], 16;\n"
                 :: "r"(dst_smem), "l"(src));
}

// One DF2T step, all coefficient multiplies in FFMA-imm form (rt_SMSP=1).
__device__ __forceinline__ float iir_step(float xv, float& z0, float& z1,
                                          float& z2, float& z3) {
    float yv = fmaf(CB0, xv, z0);
    z0 = fmaf(CB1, xv, z1); z0 = fmaf(CNA1, yv, z0);
    z1 = fmaf(CB2, xv, z2); z1 = fmaf(CNA2, yv, z1);
    z2 = fmaf(CB3, xv, z3); z2 = fmaf(CNA3, yv, z2);
    z3 = CB4 * xv;          z3 = fmaf(CNA4, yv, z3);
    return yv;
}

__global__ void __launch_bounds__(CPB, 12) fused_kernel(const float* __restrict__ x,
                                                        float* __restrict__ y,
                                                        Params P) {
    // main region + 32-float pad region (words REGION..REGION+31) for the
    // block-leading chunk's warmup window; unified addressing (wk = 0 there).
    __shared__ float4 smv[(REGION + W_WARM) / 4];
    float* sm = reinterpret_cast<float*>(smv);

    const int t   = threadIdx.x;
    const int blk = blockIdx.x;
    const int rb  = blk & (RB_PER_ROW - 1);
    const size_t gbase = (size_t)(blk >> 4) * T_LEN + (size_t)rb * REGION;

    // ---- stage: coalesced 16B cp.async -> swizzled smem ----
    const float4* xin = reinterpret_cast<const float4*>(x + gbase);
    unsigned smb = (unsigned)__cvta_generic_to_shared(sm);
#pragma unroll
    for (int i = 0; i < REGION / (4 * CPB); i++) {   // 8 iters
        int vidx = i * CPB + t;
        int c = vidx >> 3;                // 8 float4 per chunk
        int j = (vidx & 7) * 4;
        cpa16(smb + sidx4(c, j) * 4u, xin + vidx);
    }
    if (t < W_WARM / 4) {                 // pad: x[block_start-32 .. -1]
        float4 d = make_float4(0.f, 0.f, 0.f, 0.f);
        if (rb != 0)
            d = reinterpret_cast<const float4*>(x + gbase - W_WARM)[t];
        reinterpret_cast<float4*>(&sm[REGION])[t] = d;
    }
    asm volatile("cp.async.commit_group;\n");
    asm volatile("cp.async.wait_group 0;\n");
    __syncthreads();

    // ---- warmup: state = sum over previous 32 samples, w_j = A^(31-j) g ----
    // Window == previous chunk (t>0) or the pad region (t==0; zeros at row
    // start reproduce the zero-initial-condition state exactly).
    float z0 = 0.f, z1 = 0.f, z2 = 0.f, z3 = 0.f;
    {
        const int wbase = (t > 0) ? (t - 1) * L_CHUNK : REGION;
        const int wk    = (t > 0) ? ((t - 1) & 7) << 2 : 0;
#pragma unroll
        for (int q = 0; q < W_WARM / 4; q++) {
            float4 xv = *reinterpret_cast<const float4*>(&sm[wbase + ((4 * q) ^ wk)]);
            float4 w0 = P.wq4[4 * q + 0], w1 = P.wq4[4 * q + 1];
            float4 w2 = P.wq4[4 * q + 2], w3 = P.wq4[4 * q + 3];
            z0 = fmaf(w0.x, xv.x, z0); z1 = fmaf(w0.y, xv.x, z1);
            z2 = fmaf(w0.z, xv.x, z2); z3 = fmaf(w0.w, xv.x, z3);
            z0 = fmaf(w1.x, xv.y, z0); z1 = fmaf(w1.y, xv.y, z1);
            z2 = fmaf(w1.z, xv.y, z2); z3 = fmaf(w1.w, xv.y, z3);
            z0 = fmaf(w2.x, xv.z, z0); z1 = fmaf(w2.y, xv.z, z1);
            z2 = fmaf(w2.z, xv.z, z2); z3 = fmaf(w2.w, xv.z, z3);
            z0 = fmaf(w3.x, xv.w, z0); z1 = fmaf(w3.y, xv.w, z1);
            z2 = fmaf(w3.z, xv.w, z2); z3 = fmaf(w3.w, xv.w, z3);
        }
    }
    __syncthreads();   // all warmup reads done before in-place overwrite

    // ---- main: DF2T over own chunk (vectorized smem IO), y in place ----
#pragma unroll
    for (int q = 0; q < L_CHUNK / 4; q++) {
        float4* ap = reinterpret_cast<float4*>(&sm[sidx4(t, 4 * q)]);
        float4 xv = *ap;
        float4 ov;
        ov.x = iir_step(xv.x, z0, z1, z2, z3);
        ov.y = iir_step(xv.y, z0, z1, z2, z3);
        ov.z = iir_step(xv.z, z0, z1, z2, z3);
        ov.w = iir_step(xv.w, z0, z1, z2, z3);
        *ap = ov;
    }
    __syncthreads();

    // ---- output: swizzled LDS.128 -> coalesced STG.128 ----
    float4* yout = reinterpret_cast<float4*>(y + gbase);
#pragma unroll
    for (int i = 0; i < REGION / (4 * CPB); i++) {
        int vidx = i * CPB + t;
        int c = vidx >> 3;
        int j = (vidx & 7) * 4;
        yout[vidx] = *reinterpret_cast<const float4*>(&sm[sidx4(c, j)]);
    }
}

// ---------------- host ----------------

extern "C" void kernel_launch(void* const* d_in, const int* in_sizes, int n_in,
                              void* d_out, int out_size) {
    const float* x = (const float*)d_in[0];
    float* y = (float*)d_out;

    // Same coefficients as the device literals, in double for weight generation.
    const double kd = 0.010209481;
    const double bcoef[5] = { kd, 4.0 * kd, 6.0 * kd, 4.0 * kd, kd };
    const double acoef[5] = { 1.0, -1.96842778, 1.73586071,
                              -0.72447081, 0.12038960 };

    // state transition: z' = A z + g x  (DF2T with y eliminated)
    double A[16] = {0};
    for (int i = 0; i < 4; i++) {
        A[i * 4 + 0] -= acoef[i + 1];
        if (i < 3) A[i * 4 + (i + 1)] += 1.0;
    }
    double g[4];
    for (int i = 0; i < 4; i++) g[i] = bcoef[i + 1] - acoef[i + 1] * bcoef[0];

    Params P;
    // warmup weights: w_j = A^(W-1-j) g  (oldest sample gets highest power)
    double wv[4] = { g[0], g[1], g[2], g[3] };
    for (int j = W_WARM - 1; j >= 0; j--) {
        P.wq4[j] = make_float4((float)wv[0], (float)wv[1],
                               (float)wv[2], (float)wv[3]);
        double nv[4];
        for (int i = 0; i < 4; i++) {
            nv[i] = 0.0;
            for (int k2 = 0; k2 < 4; k2++) nv[i] += A[i * 4 + k2] * wv[k2];
        }
        for (int i = 0; i < 4; i++) wv[i] = nv[i];
    }

    fused_kernel<<<NBLK, CPB>>>(x, y, P);
}